// round 10
// baseline (speedup 1.0000x reference)
#include <cuda_runtime.h>
#include <cstdint>

#define UNITS        32768
#define PACKED_WORDS 1024                 // uint32 words per weight row
#define PACKED_VEC   (PACKED_WORDS / 4)   // 256 uint4 per row
#define OUT_WORDS    (UNITS / 32)         // 1024 packed output words
#define WARPS_PER_BLOCK 32
#define THREADS (WARPS_PER_BLOCK * 32)
#define WORDS_PER_BLOCK 2                 // each block produces 2 output words

__global__ __launch_bounds__(THREADS, 2)
void bitdense_kernel(const uint32_t* __restrict__ inp,
                     const uint4*    __restrict__ w,
                     const int*      __restrict__ b,
                     float*          __restrict__ out)
{
    __shared__ uint4 s_in[PACKED_VEC];                       // 4 KB input stage
    __shared__ int   s_sign[WORDS_PER_BLOCK][WARPS_PER_BLOCK];

    const int tid  = threadIdx.x;
    const int warp = tid >> 5;
    const int lane = tid & 31;

    if (tid < PACKED_VEC) {
        s_in[tid] = ((const uint4*)inp)[tid];
    }
    __syncthreads();

    // This block produces output words oidx0 and oidx0+1.
    // Warp 'warp' handles unit (oidx*32 + warp) of each word.
    const int oidx0 = blockIdx.x * WORDS_PER_BLOCK;
    const int u0 = (oidx0 + 0) * WARPS_PER_BLOCK + warp;
    const int u1 = (oidx0 + 1) * WARPS_PER_BLOCK + warp;
    const uint4* row0 = w + (size_t)u0 * PACKED_VEC;
    const uint4* row1 = w + (size_t)u1 * PACKED_VEC;

    // Interleave both rows in one loop: loads for both issue together
    // (~2x per-warp MLP), no REDUX wait between words, no mid-kernel
    // __syncthreads -> the block's load stream is continuous.
    int acc0 = 0, acc1 = 0;
    #pragma unroll
    for (int i = 0; i < 8; i++) {
        uint4 iv = s_in[lane + i * 32];
        uint4 w0 = row0[lane + i * 32];
        uint4 w1 = row1[lane + i * 32];
        acc0 += __popc(w0.x ^ iv.x) + __popc(w0.y ^ iv.y)
              + __popc(w0.z ^ iv.z) + __popc(w0.w ^ iv.w);
        acc1 += __popc(w1.x ^ iv.x) + __popc(w1.y ^ iv.y)
              + __popc(w1.z ^ iv.z) + __popc(w1.w ^ iv.w);
    }

    int ones0 = __reduce_add_sync(0xffffffffu, acc0);
    int ones1 = __reduce_add_sync(0xffffffffu, acc1);

    if (lane == 0) {
        s_sign[0][warp] = (32768 - 2 * ones0 + b[u0] < 0) ? 1 : 0;
        s_sign[1][warp] = (32768 - 2 * ones1 + b[u1] < 0) ? 1 : 0;
    }
    __syncthreads();   // single terminal sync

    // Parallel epilogue: warp k packs word k.
    // packbits layout: unit u lands at word-bit (u ^ 7) (MSB-first per byte,
    // bytes little-endian); XOR-7 is self-inverse -> lane i votes sign of
    // unit (i ^ 7) and ballot emits the word directly.
    if (warp < WORDS_PER_BLOCK) {
        unsigned wrd = __ballot_sync(0xffffffffu, s_sign[warp][lane ^ 7]);
        if (lane == 0) {
            // Expected = packed word viewed as SIGNED int32, compared by
            // value against our float32 output buffer.
            out[oidx0 + warp] = (float)(int32_t)wrd;
        }
    }
}

// Zero any tail of d_out beyond OUT_WORDS (defensive).
__global__ void tail_zero_kernel(float* __restrict__ out, int begin, int n)
{
    int i = begin + blockIdx.x * blockDim.x + threadIdx.x;
    if (i < n) out[i] = 0.0f;
}

extern "C" void kernel_launch(void* const* d_in, const int* in_sizes, int n_in,
                              void* d_out, int out_size)
{
    // Bind inputs by relative size (robust to metadata ordering):
    // largest buffer = w, smallest = inputs, remaining = b.
    int iw = 0, ii = 0;
    for (int i = 1; i < n_in; i++) {
        if (in_sizes[i] > in_sizes[iw]) iw = i;
        if (in_sizes[i] < in_sizes[ii]) ii = i;
    }
    int ib = 0;
    for (int i = 0; i < n_in; i++) if (i != iw && i != ii) { ib = i; break; }

    const uint32_t* inp = (const uint32_t*)d_in[ii];  // [1024] packed input bits
    const uint4*    w   = (const uint4*)   d_in[iw];  // [32768,1024] packed weights
    const int*      b   = (const int*)     d_in[ib];  // [32768] bias
    float*          out = (float*)         d_out;     // [1024] packed words (signed value)

    dim3 grid(OUT_WORDS / WORDS_PER_BLOCK);  // 512 blocks x 2 output words
    dim3 block(THREADS);                     // 32 warps; warp w: unit w of each word
    bitdense_kernel<<<grid, block>>>(inp, w, b, out);

    if (out_size > OUT_WORDS) {
        int tail = out_size - OUT_WORDS;
        tail_zero_kernel<<<(tail + 255) / 256, 256>>>(out, OUT_WORDS, out_size);
    }
}

// round 11
// speedup vs baseline: 1.0347x; 1.0347x over previous
#include <cuda_runtime.h>
#include <cstdint>

#define UNITS        32768
#define PACKED_WORDS 1024                 // uint32 words per weight row
#define PACKED_VEC   (PACKED_WORDS / 4)   // 256 uint4 per row
#define OUT_WORDS    (UNITS / 32)         // 1024 packed output words
#define WARPS_PER_BLOCK 32
#define THREADS (WARPS_PER_BLOCK * 32)
#define WORDS_PER_BLOCK 2                 // each block produces 2 output words

__global__ __launch_bounds__(THREADS, 2)
void bitdense_kernel(const uint32_t* __restrict__ inp,
                     const uint4*    __restrict__ w,
                     const int*      __restrict__ b,
                     float*          __restrict__ out)
{
    __shared__ uint4 s_in[PACKED_VEC];   // 4 KB input stage (once per block)
    __shared__ int   s_sign[WARPS_PER_BLOCK];

    const int tid  = threadIdx.x;
    const int warp = tid >> 5;
    const int lane = tid & 31;

    if (tid < PACKED_VEC) {
        s_in[tid] = ((const uint4*)inp)[tid];
    }
    __syncthreads();

    #pragma unroll
    for (int word = 0; word < WORDS_PER_BLOCK; word++) {
        const int oidx = blockIdx.x * WORDS_PER_BLOCK + word;
        // One warp per unit (weight row), processed sequentially: one 4 KB
        // contiguous stream per warp at a time (best DRAM page locality;
        // fits the 32-reg budget with all 8 LDG.128 batched).
        const int unit = oidx * WARPS_PER_BLOCK + warp;
        const uint4* row = w + (size_t)unit * PACKED_VEC;

        int acc = 0;
        #pragma unroll
        for (int i = 0; i < 8; i++) {
            // __ldcg: L2-only (no L1 allocation) — the 134 MB weight stream
            // has zero reuse; skip the L1 pass-through entirely.
            uint4 wv = __ldcg(&row[lane + i * 32]);
            uint4 iv = s_in[lane + i * 32];
            acc += __popc(wv.x ^ iv.x) + __popc(wv.y ^ iv.y)
                 + __popc(wv.z ^ iv.z) + __popc(wv.w ^ iv.w);
        }

        // Single-instruction warp sum (REDUX.SUM)
        int ones = __reduce_add_sync(0xffffffffu, acc);

        if (lane == 0) {
            int o = 32768 - 2 * ones + b[unit];
            s_sign[warp] = (o < 0) ? 1 : 0;
        }
        __syncthreads();

        // Pack 32 signs: unit u lands at word-bit (u ^ 7) (packbits MSB-first
        // per byte, bytes little-endian). XOR-7 is self-inverse -> lane i
        // votes the sign of unit (i ^ 7); ballot emits the word directly.
        if (warp == 0) {
            unsigned wrd = __ballot_sync(0xffffffffu, s_sign[lane ^ 7]);
            if (lane == 0) {
                // Expected = packed word viewed as SIGNED int32, compared by
                // value against our float32 output buffer.
                out[oidx] = (float)(int32_t)wrd;
            }
        }
        if (word + 1 < WORDS_PER_BLOCK) __syncthreads();
    }
}

// Zero any tail of d_out beyond OUT_WORDS (defensive).
__global__ void tail_zero_kernel(float* __restrict__ out, int begin, int n)
{
    int i = begin + blockIdx.x * blockDim.x + threadIdx.x;
    if (i < n) out[i] = 0.0f;
}

extern "C" void kernel_launch(void* const* d_in, const int* in_sizes, int n_in,
                              void* d_out, int out_size)
{
    // Bind inputs by relative size (robust to metadata ordering):
    // largest buffer = w, smallest = inputs, remaining = b.
    int iw = 0, ii = 0;
    for (int i = 1; i < n_in; i++) {
        if (in_sizes[i] > in_sizes[iw]) iw = i;
        if (in_sizes[i] < in_sizes[ii]) ii = i;
    }
    int ib = 0;
    for (int i = 0; i < n_in; i++) if (i != iw && i != ii) { ib = i; break; }

    const uint32_t* inp = (const uint32_t*)d_in[ii];  // [1024] packed input bits
    const uint4*    w   = (const uint4*)   d_in[iw];  // [32768,1024] packed weights
    const int*      b   = (const int*)     d_in[ib];  // [32768] bias
    float*          out = (float*)         d_out;     // [1024] packed words (signed value)

    dim3 grid(OUT_WORDS / WORDS_PER_BLOCK);  // 512 blocks x 2 output words
    dim3 block(THREADS);                     // 32 warps, one unit each per word
    bitdense_kernel<<<grid, block>>>(inp, w, b, out);

    if (out_size > OUT_WORDS) {
        int tail = out_size - OUT_WORDS;
        tail_zero_kernel<<<(tail + 255) / 256, 256>>>(out, OUT_WORDS, out_size);
    }
}